// round 6
// baseline (speedup 1.0000x reference)
#include <cuda_runtime.h>
#include <math.h>

#define Bn 4
#define Dm 1024
#define Sn 2048
#define Hn 16
#define HD 64

// ---------------- scratch (static device memory, no allocs) ----------------
__device__ float g_Xt[Bn*Sn*Dm];  // x + pe, transposed to [B,S,D]
__device__ float g_Q [Bn*Sn*Dm];
__device__ float g_K [Bn*Sn*Dm];
__device__ float g_V [Bn*Sn*Dm];
__device__ float g_AO[Bn*Sn*Dm];  // attention out [B,S,D]
__device__ float g_P [Bn*Sn*Dm];  // out proj [B,S,D]

// ---------------- pos-encoding + transpose: x[b,d,s] -> Xt[b,s,d] ----------
__global__ void k_prep(const float* __restrict__ x){
    __shared__ float t[32][33];
    int b  = blockIdx.z;
    int d0 = blockIdx.y * 32, s0 = blockIdx.x * 32;
    const float NEG = -9.210340371976184f / (float)Dm;   // -ln(10000)/D
    #pragma unroll
    for (int k = 0; k < 4; k++){
        int d = d0 + threadIdx.y + k*8;
        int s = s0 + threadIdx.x;
        float v = x[(b*Dm + d)*Sn + s];
        int de = d & ~1;
        float ang = (float)s * __expf((float)de * NEG);
        v += (d & 1) ? cosf(ang) : sinf(ang);
        t[threadIdx.y + k*8][threadIdx.x] = v;
    }
    __syncthreads();
    #pragma unroll
    for (int k = 0; k < 4; k++){
        int s = s0 + threadIdx.y + k*8;
        int d = d0 + threadIdx.x;
        g_Xt[(b*Sn + s)*Dm + d] = t[threadIdx.x][threadIdx.y + k*8];
    }
}

// ---------------- SGEMM: C[n,m] = sum_k A[n,k]*W[m,k] + bias[m] ------------
// A: [8192,1024] row-major, W: [1024,1024] row-major, NT gemm.
// 128x128 tile, BK=16, 256 threads, 8x8 microtile, strided mapping.
__global__ __launch_bounds__(256) void k_gemm(const float* __restrict__ A,
                                              const float* __restrict__ W,
                                              const float* __restrict__ bias,
                                              float* __restrict__ C){
    __shared__ float As[128][17];
    __shared__ float Bs[128][17];
    int tid = threadIdx.x;
    int cx = tid & 15, ry = tid >> 4;            // cols strided by 16 via cx, rows via ry
    int m0 = blockIdx.x * 128, n0 = blockIdx.y * 128;

    float acc[8][8];
    #pragma unroll
    for (int i = 0; i < 8; i++)
        #pragma unroll
        for (int j = 0; j < 8; j++) acc[i][j] = 0.f;

    for (int kt = 0; kt < Dm/16; kt++){
        int k0 = kt * 16;
        #pragma unroll
        for (int r = 0; r < 2; r++){
            int f   = tid + 256*r;               // 0..511 float4 slots
            int row = f >> 2, kq = f & 3;
            float4 av = *(const float4*)(A + (n0+row)*Dm + k0 + 4*kq);
            As[row][4*kq+0]=av.x; As[row][4*kq+1]=av.y;
            As[row][4*kq+2]=av.z; As[row][4*kq+3]=av.w;
            float4 bv = *(const float4*)(W + (m0+row)*Dm + k0 + 4*kq);
            Bs[row][4*kq+0]=bv.x; Bs[row][4*kq+1]=bv.y;
            Bs[row][4*kq+2]=bv.z; Bs[row][4*kq+3]=bv.w;
        }
        __syncthreads();
        #pragma unroll
        for (int kk = 0; kk < 16; kk++){
            float a[8], b[8];
            #pragma unroll
            for (int i = 0; i < 8; i++) a[i] = As[ry + 16*i][kk];   // broadcast
            #pragma unroll
            for (int j = 0; j < 8; j++) b[j] = Bs[cx + 16*j][kk];   // lane-consecutive
            #pragma unroll
            for (int i = 0; i < 8; i++)
                #pragma unroll
                for (int j = 0; j < 8; j++) acc[i][j] += a[i]*b[j];
        }
        __syncthreads();
    }

    float bb[8];
    #pragma unroll
    for (int j = 0; j < 8; j++) bb[j] = bias[m0 + cx + 16*j];
    #pragma unroll
    for (int i = 0; i < 8; i++){
        int n = n0 + ry + 16*i;
        #pragma unroll
        for (int j = 0; j < 8; j++)
            C[n*Dm + m0 + cx + 16*j] = acc[i][j] + bb[j];
    }
}

// ---------------- flash attention fp32 -------------------------------------
// BM=128 queries, BN=64 keys, hd=64, 128 threads (16 qx x 8 ky), 8x8 microtile.
// q rows = qx + 16*i (strided), key/hd cols = 8*ky + j (consecutive).
#define QS_LD 65
#define KS_LD 68
__global__ __launch_bounds__(128) void k_flash(const float* __restrict__ Q,
                                               const float* __restrict__ K,
                                               const float* __restrict__ V,
                                               float* __restrict__ O){
    extern __shared__ float sm[];
    float* Qs   = sm;                      // [128][65]  (q, d)
    float* Ps   = Qs + 128*QS_LD;          // [128][65]  scores/probs (q, k)
    float* Ks   = Ps + 128*QS_LD;          // [64][68]   (k, d)
    float* Vs   = Ks + 64*KS_LD;           // [64][68]   (k, d)
    float* corr = Vs + 64*KS_LD;           // [128]

    int tid = threadIdx.x;
    int qx = tid & 15, ky = tid >> 4;
    int q0 = blockIdx.x * 128;
    int h  = blockIdx.y, b = blockIdx.z;
    int base = (b*Sn)*Dm + h*HD;           // + s*Dm + d

    // load Q tile, fold 1/sqrt(64) scale
    #pragma unroll
    for (int r = 0; r < 16; r++){
        int f = tid + 128*r;               // 2048 float4 slots
        int q = f >> 4, dq = f & 15;
        float4 v = *(const float4*)(Q + base + (q0+q)*Dm + 4*dq);
        float* dst = &Qs[q*QS_LD + 4*dq];
        dst[0]=v.x*0.125f; dst[1]=v.y*0.125f; dst[2]=v.z*0.125f; dst[3]=v.w*0.125f;
    }

    float m = -INFINITY, l = 0.f;
    float oacc[8][8];
    #pragma unroll
    for (int i = 0; i < 8; i++)
        #pragma unroll
        for (int j = 0; j < 8; j++) oacc[i][j] = 0.f;

    for (int kt = 0; kt < Sn/64; kt++){
        __syncthreads();                   // prev PV done before overwrite
        #pragma unroll
        for (int r = 0; r < 8; r++){
            int f = tid + 128*r;           // 1024 float4 slots
            int kk = f >> 4, dq = f & 15;
            int g = base + (kt*64 + kk)*Dm + 4*dq;
            *(float4*)&Ks[kk*KS_LD + 4*dq] = *(const float4*)(K + g);
            *(float4*)&Vs[kk*KS_LD + 4*dq] = *(const float4*)(V + g);
        }
        __syncthreads();

        // S = Q K^T (scaled)
        float sacc[8][8];
        #pragma unroll
        for (int i = 0; i < 8; i++)
            #pragma unroll
            for (int j = 0; j < 8; j++) sacc[i][j] = 0.f;
        #pragma unroll 4
        for (int kk = 0; kk < 64; kk++){
            float a[8], bv[8];
            #pragma unroll
            for (int i = 0; i < 8; i++) a[i]  = Qs[(qx + 16*i)*QS_LD + kk];
            #pragma unroll
            for (int j = 0; j < 8; j++) bv[j] = Ks[(8*ky + j)*KS_LD + kk];
            #pragma unroll
            for (int i = 0; i < 8; i++)
                #pragma unroll
                for (int j = 0; j < 8; j++) sacc[i][j] += a[i]*bv[j];
        }
        #pragma unroll
        for (int i = 0; i < 8; i++)
            #pragma unroll
            for (int j = 0; j < 8; j++)
                Ps[(qx + 16*i)*QS_LD + 8*ky + j] = sacc[i][j];
        __syncthreads();

        // online softmax: thread tid owns row q=tid
        {
            float* row = &Ps[tid*QS_LD];
            float mt = row[0];
            #pragma unroll 8
            for (int k = 1; k < 64; k++) mt = fmaxf(mt, row[k]);
            float mn = fmaxf(m, mt);
            float c  = __expf(m - mn);
            float sum = 0.f;
            #pragma unroll 8
            for (int k = 0; k < 64; k++){
                float p = __expf(row[k] - mn);
                row[k] = p;
                sum += p;
            }
            l = l*c + sum;
            m = mn;
            corr[tid] = c;
        }
        __syncthreads();

        // rescale O, accumulate P·V
        float cr[8];
        #pragma unroll
        for (int i = 0; i < 8; i++) cr[i] = corr[qx + 16*i];
        #pragma unroll
        for (int i = 0; i < 8; i++)
            #pragma unroll
            for (int j = 0; j < 8; j++) oacc[i][j] *= cr[i];
        #pragma unroll 4
        for (int kk = 0; kk < 64; kk++){
            float p[8], vv[8];
            #pragma unroll
            for (int i = 0; i < 8; i++) p[i]  = Ps[(qx + 16*i)*QS_LD + kk];
            #pragma unroll
            for (int j = 0; j < 8; j++) vv[j] = Vs[kk*KS_LD + 8*ky + j];
            #pragma unroll
            for (int i = 0; i < 8; i++)
                #pragma unroll
                for (int j = 0; j < 8; j++) oacc[i][j] += p[i]*vv[j];
        }
    }

    // finalize: 1/l per row, stage through smem for coalesced store
    __syncthreads();
    corr[tid] = 1.f / l;
    __syncthreads();
    float li[8];
    #pragma unroll
    for (int i = 0; i < 8; i++) li[i] = corr[qx + 16*i];
    #pragma unroll
    for (int i = 0; i < 8; i++)
        #pragma unroll
        for (int j = 0; j < 8; j++)
            Ps[(qx + 16*i)*QS_LD + 8*ky + j] = oacc[i][j] * li[i];
    __syncthreads();
    #pragma unroll
    for (int r = 0; r < 16; r++){
        int f = tid + 128*r;
        int q = f >> 4, dc = (f & 15) * 4;
        float4 o;
        o.x = Ps[q*QS_LD + dc + 0];
        o.y = Ps[q*QS_LD + dc + 1];
        o.z = Ps[q*QS_LD + dc + 2];
        o.w = Ps[q*QS_LD + dc + 3];
        *(float4*)(O + base + (q0+q)*Dm + dc) = o;
    }
}

// ---------------- final transpose: P[b,s,d] -> out[b,d,s] ------------------
__global__ void k_tout(const float* __restrict__ P, float* __restrict__ out){
    __shared__ float t[32][33];
    int b  = blockIdx.z;
    int d0 = blockIdx.y * 32, s0 = blockIdx.x * 32;
    #pragma unroll
    for (int k = 0; k < 4; k++){
        int s = s0 + threadIdx.y + k*8;
        int d = d0 + threadIdx.x;
        t[threadIdx.y + k*8][threadIdx.x] = P[(b*Sn + s)*Dm + d];
    }
    __syncthreads();
    #pragma unroll
    for (int k = 0; k < 4; k++){
        int d = d0 + threadIdx.y + k*8;
        int s = s0 + threadIdx.x;
        out[(b*Dm + d)*Sn + s] = t[threadIdx.x][threadIdx.y + k*8];
    }
}

// ---------------- launch ----------------------------------------------------
extern "C" void kernel_launch(void* const* d_in, const int* in_sizes, int n_in,
                              void* d_out, int out_size){
    const float* x  = (const float*)d_in[0];
    const float* Wq = (const float*)d_in[1];
    const float* bq = (const float*)d_in[2];
    const float* Wk = (const float*)d_in[3];
    const float* bk = (const float*)d_in[4];
    const float* Wv = (const float*)d_in[5];
    const float* bv = (const float*)d_in[6];
    const float* Wo = (const float*)d_in[7];
    const float* bo = (const float*)d_in[8];
    float* out = (float*)d_out;

    float *pXt, *pQ, *pK, *pV, *pAO, *pP;
    cudaGetSymbolAddress((void**)&pXt, g_Xt);
    cudaGetSymbolAddress((void**)&pQ,  g_Q);
    cudaGetSymbolAddress((void**)&pK,  g_K);
    cudaGetSymbolAddress((void**)&pV,  g_V);
    cudaGetSymbolAddress((void**)&pAO, g_AO);
    cudaGetSymbolAddress((void**)&pP,  g_P);

    const int FLASH_SMEM = (128*QS_LD + 128*QS_LD + 64*KS_LD + 64*KS_LD + 128) * 4;
    cudaFuncSetAttribute(k_flash, cudaFuncAttributeMaxDynamicSharedMemorySize, FLASH_SMEM);

    k_prep<<<dim3(Sn/32, Dm/32, Bn), dim3(32, 8)>>>(x);

    dim3 gg(Dm/128, (Bn*Sn)/128);
    k_gemm<<<gg, 256>>>(pXt, Wq, bq, pQ);
    k_gemm<<<gg, 256>>>(pXt, Wk, bk, pK);
    k_gemm<<<gg, 256>>>(pXt, Wv, bv, pV);

    k_flash<<<dim3(Sn/128, Hn, Bn), 128, FLASH_SMEM>>>(pQ, pK, pV, pAO);

    k_gemm<<<gg, 256>>>(pAO, Wo, bo, pP);

    k_tout<<<dim3(Sn/32, Dm/32, Bn), dim3(32, 8)>>>(pP, out);
}

// round 7
// speedup vs baseline: 1.0539x; 1.0539x over previous
#include <cuda_runtime.h>
#include <math.h>

#define Bn 4
#define Dm 1024
#define Sn 2048
#define Hn 16
#define HD 64

// ---------------- scratch (static device memory, no allocs) ----------------
__device__ float g_Xt[Bn*Sn*Dm];  // x + pe, transposed to [B,S,D]
__device__ float g_Q [Bn*Sn*Dm];
__device__ float g_K [Bn*Sn*Dm];
__device__ float g_V [Bn*Sn*Dm];
__device__ float g_AO[Bn*Sn*Dm];  // attention out [B,S,D]
__device__ float g_P [Bn*Sn*Dm];  // out proj [B,S,D]

// ---------------- pos-encoding + transpose: x[b,d,s] -> Xt[b,s,d] ----------
__global__ void k_prep(const float* __restrict__ x){
    __shared__ float t[32][33];
    int b  = blockIdx.z;
    int d0 = blockIdx.y * 32, s0 = blockIdx.x * 32;
    const float NEG = -9.210340371976184f / (float)Dm;   // -ln(10000)/D
    #pragma unroll
    for (int k = 0; k < 4; k++){
        int d = d0 + threadIdx.y + k*8;
        int s = s0 + threadIdx.x;
        float v = x[(b*Dm + d)*Sn + s];
        int de = d & ~1;
        float ang = (float)s * __expf((float)de * NEG);
        v += (d & 1) ? cosf(ang) : sinf(ang);
        t[threadIdx.y + k*8][threadIdx.x] = v;
    }
    __syncthreads();
    #pragma unroll
    for (int k = 0; k < 4; k++){
        int s = s0 + threadIdx.y + k*8;
        int d = d0 + threadIdx.x;
        g_Xt[(b*Sn + s)*Dm + d] = t[threadIdx.x][threadIdx.y + k*8];
    }
}

// ---------------- SGEMM: C[n,m] = sum_k A[n,k]*W[m,k] + bias[m] ------------
// A: [8192,1024] row-major, W: [1024,1024] row-major, NT gemm.
// 128x128 tile, BK=16, 256 threads, 8x8 microtile, strided mapping.
__global__ __launch_bounds__(256) void k_gemm(const float* __restrict__ A,
                                              const float* __restrict__ W,
                                              const float* __restrict__ bias,
                                              float* __restrict__ C){
    __shared__ float As[128][17];
    __shared__ float Bs[128][17];
    int tid = threadIdx.x;
    int cx = tid & 15, ry = tid >> 4;            // cols strided by 16 via cx, rows via ry
    int m0 = blockIdx.x * 128, n0 = blockIdx.y * 128;

    float acc[8][8];
    #pragma unroll
    for (int i = 0; i < 8; i++)
        #pragma unroll
        for (int j = 0; j < 8; j++) acc[i][j] = 0.f;

    for (int kt = 0; kt < Dm/16; kt++){
        int k0 = kt * 16;
        #pragma unroll
        for (int r = 0; r < 2; r++){
            int f   = tid + 256*r;               // 0..511 float4 slots
            int row = f >> 2, kq = f & 3;
            float4 av = *(const float4*)(A + (n0+row)*Dm + k0 + 4*kq);
            As[row][4*kq+0]=av.x; As[row][4*kq+1]=av.y;
            As[row][4*kq+2]=av.z; As[row][4*kq+3]=av.w;
            float4 bv = *(const float4*)(W + (m0+row)*Dm + k0 + 4*kq);
            Bs[row][4*kq+0]=bv.x; Bs[row][4*kq+1]=bv.y;
            Bs[row][4*kq+2]=bv.z; Bs[row][4*kq+3]=bv.w;
        }
        __syncthreads();
        #pragma unroll
        for (int kk = 0; kk < 16; kk++){
            float a[8], b[8];
            #pragma unroll
            for (int i = 0; i < 8; i++) a[i] = As[ry + 16*i][kk];   // broadcast
            #pragma unroll
            for (int j = 0; j < 8; j++) b[j] = Bs[cx + 16*j][kk];   // lane-consecutive
            #pragma unroll
            for (int i = 0; i < 8; i++)
                #pragma unroll
                for (int j = 0; j < 8; j++) acc[i][j] += a[i]*b[j];
        }
        __syncthreads();
    }

    float bb[8];
    #pragma unroll
    for (int j = 0; j < 8; j++) bb[j] = bias[m0 + cx + 16*j];
    #pragma unroll
    for (int i = 0; i < 8; i++){
        int n = n0 + ry + 16*i;
        #pragma unroll
        for (int j = 0; j < 8; j++)
            C[n*Dm + m0 + cx + 16*j] = acc[i][j] + bb[j];
    }
}

// ---------------- flash attention fp32 -------------------------------------
// BM=128 queries, BN=64 keys, hd=64, 128 threads (16 qx x 8 ky), 8x8 microtile.
// q rows = qx + 16*i (strided), key/hd cols = 8*ky + j (consecutive).
#define QS_LD 65
#define KS_LD 68
__global__ __launch_bounds__(128) void k_flash(const float* __restrict__ Q,
                                               const float* __restrict__ K,
                                               const float* __restrict__ V,
                                               float* __restrict__ O){
    extern __shared__ float sm[];
    float* Qs   = sm;                      // [128][65]  (q, d)
    float* Ps   = Qs + 128*QS_LD;          // [128][65]  scores/probs (q, k)
    float* Ks   = Ps + 128*QS_LD;          // [64][68]   (k, d)
    float* Vs   = Ks + 64*KS_LD;           // [64][68]   (k, d)
    float* corr = Vs + 64*KS_LD;           // [128]

    int tid = threadIdx.x;
    int qx = tid & 15, ky = tid >> 4;
    int q0 = blockIdx.x * 128;
    int h  = blockIdx.y, b = blockIdx.z;
    int base = (b*Sn)*Dm + h*HD;           // + s*Dm + d

    // load Q tile, fold 1/sqrt(64) scale
    #pragma unroll
    for (int r = 0; r < 16; r++){
        int f = tid + 128*r;               // 2048 float4 slots
        int q = f >> 4, dq = f & 15;
        float4 v = *(const float4*)(Q + base + (q0+q)*Dm + 4*dq);
        float* dst = &Qs[q*QS_LD + 4*dq];
        dst[0]=v.x*0.125f; dst[1]=v.y*0.125f; dst[2]=v.z*0.125f; dst[3]=v.w*0.125f;
    }

    float m = -INFINITY, l = 0.f;
    float oacc[8][8];
    #pragma unroll
    for (int i = 0; i < 8; i++)
        #pragma unroll
        for (int j = 0; j < 8; j++) oacc[i][j] = 0.f;

    for (int kt = 0; kt < Sn/64; kt++){
        __syncthreads();                   // prev PV done before overwrite
        #pragma unroll
        for (int r = 0; r < 8; r++){
            int f = tid + 128*r;           // 1024 float4 slots
            int kk = f >> 4, dq = f & 15;
            int g = base + (kt*64 + kk)*Dm + 4*dq;
            *(float4*)&Ks[kk*KS_LD + 4*dq] = *(const float4*)(K + g);
            *(float4*)&Vs[kk*KS_LD + 4*dq] = *(const float4*)(V + g);
        }
        __syncthreads();

        // S = Q K^T (scaled)
        float sacc[8][8];
        #pragma unroll
        for (int i = 0; i < 8; i++)
            #pragma unroll
            for (int j = 0; j < 8; j++) sacc[i][j] = 0.f;
        #pragma unroll 4
        for (int kk = 0; kk < 64; kk++){
            float a[8], bv[8];
            #pragma unroll
            for (int i = 0; i < 8; i++) a[i]  = Qs[(qx + 16*i)*QS_LD + kk];
            #pragma unroll
            for (int j = 0; j < 8; j++) bv[j] = Ks[(8*ky + j)*KS_LD + kk];
            #pragma unroll
            for (int i = 0; i < 8; i++)
                #pragma unroll
                for (int j = 0; j < 8; j++) sacc[i][j] += a[i]*bv[j];
        }
        #pragma unroll
        for (int i = 0; i < 8; i++)
            #pragma unroll
            for (int j = 0; j < 8; j++)
                Ps[(qx + 16*i)*QS_LD + 8*ky + j] = sacc[i][j];
        __syncthreads();

        // online softmax: thread tid owns row q=tid
        {
            float* row = &Ps[tid*QS_LD];
            float mt = row[0];
            #pragma unroll 8
            for (int k = 1; k < 64; k++) mt = fmaxf(mt, row[k]);
            float mn = fmaxf(m, mt);
            float c  = __expf(m - mn);
            float sum = 0.f;
            #pragma unroll 8
            for (int k = 0; k < 64; k++){
                float p = __expf(row[k] - mn);
                row[k] = p;
                sum += p;
            }
            l = l*c + sum;
            m = mn;
            corr[tid] = c;
        }
        __syncthreads();

        // rescale O, accumulate P·V
        float cr[8];
        #pragma unroll
        for (int i = 0; i < 8; i++) cr[i] = corr[qx + 16*i];
        #pragma unroll
        for (int i = 0; i < 8; i++)
            #pragma unroll
            for (int j = 0; j < 8; j++) oacc[i][j] *= cr[i];
        #pragma unroll 4
        for (int kk = 0; kk < 64; kk++){
            float p[8], vv[8];
            #pragma unroll
            for (int i = 0; i < 8; i++) p[i]  = Ps[(qx + 16*i)*QS_LD + kk];
            #pragma unroll
            for (int j = 0; j < 8; j++) vv[j] = Vs[kk*KS_LD + 8*ky + j];
            #pragma unroll
            for (int i = 0; i < 8; i++)
                #pragma unroll
                for (int j = 0; j < 8; j++) oacc[i][j] += p[i]*vv[j];
        }
    }

    // finalize: 1/l per row, stage through smem for coalesced store
    __syncthreads();
    corr[tid] = 1.f / l;
    __syncthreads();
    float li[8];
    #pragma unroll
    for (int i = 0; i < 8; i++) li[i] = corr[qx + 16*i];
    #pragma unroll
    for (int i = 0; i < 8; i++)
        #pragma unroll
        for (int j = 0; j < 8; j++)
            Ps[(qx + 16*i)*QS_LD + 8*ky + j] = oacc[i][j] * li[i];
    __syncthreads();
    #pragma unroll
    for (int r = 0; r < 16; r++){
        int f = tid + 128*r;
        int q = f >> 4, dc = (f & 15) * 4;
        float4 o;
        o.x = Ps[q*QS_LD + dc + 0];
        o.y = Ps[q*QS_LD + dc + 1];
        o.z = Ps[q*QS_LD + dc + 2];
        o.w = Ps[q*QS_LD + dc + 3];
        *(float4*)(O + base + (q0+q)*Dm + dc) = o;
    }
}

// ---------------- final transpose: P[b,s,d] -> out[b,d,s] ------------------
__global__ void k_tout(const float* __restrict__ P, float* __restrict__ out){
    __shared__ float t[32][33];
    int b  = blockIdx.z;
    int d0 = blockIdx.y * 32, s0 = blockIdx.x * 32;
    #pragma unroll
    for (int k = 0; k < 4; k++){
        int s = s0 + threadIdx.y + k*8;
        int d = d0 + threadIdx.x;
        t[threadIdx.y + k*8][threadIdx.x] = P[(b*Sn + s)*Dm + d];
    }
    __syncthreads();
    #pragma unroll
    for (int k = 0; k < 4; k++){
        int d = d0 + threadIdx.y + k*8;
        int s = s0 + threadIdx.x;
        out[(b*Dm + d)*Sn + s] = t[threadIdx.x][threadIdx.y + k*8];
    }
}

// ---------------- launch ----------------------------------------------------
extern "C" void kernel_launch(void* const* d_in, const int* in_sizes, int n_in,
                              void* d_out, int out_size){
    const float* x  = (const float*)d_in[0];
    const float* Wq = (const float*)d_in[1];
    const float* bq = (const float*)d_in[2];
    const float* Wk = (const float*)d_in[3];
    const float* bk = (const float*)d_in[4];
    const float* Wv = (const float*)d_in[5];
    const float* bv = (const float*)d_in[6];
    const float* Wo = (const float*)d_in[7];
    const float* bo = (const float*)d_in[8];
    float* out = (float*)d_out;

    float *pXt, *pQ, *pK, *pV, *pAO, *pP;
    cudaGetSymbolAddress((void**)&pXt, g_Xt);
    cudaGetSymbolAddress((void**)&pQ,  g_Q);
    cudaGetSymbolAddress((void**)&pK,  g_K);
    cudaGetSymbolAddress((void**)&pV,  g_V);
    cudaGetSymbolAddress((void**)&pAO, g_AO);
    cudaGetSymbolAddress((void**)&pP,  g_P);

    const int FLASH_SMEM = (128*QS_LD + 128*QS_LD + 64*KS_LD + 64*KS_LD + 128) * 4;
    cudaFuncSetAttribute(k_flash, cudaFuncAttributeMaxDynamicSharedMemorySize, FLASH_SMEM);

    k_prep<<<dim3(Sn/32, Dm/32, Bn), dim3(32, 8)>>>(x);

    dim3 gg(Dm/128, (Bn*Sn)/128);
    k_gemm<<<gg, 256>>>(pXt, Wq, bq, pQ);
    k_gemm<<<gg, 256>>>(pXt, Wk, bk, pK);
    k_gemm<<<gg, 256>>>(pXt, Wv, bv, pV);

    k_flash<<<dim3(Sn/128, Hn, Bn), 128, FLASH_SMEM>>>(pQ, pK, pV, pAO);

    k_gemm<<<gg, 256>>>(pAO, Wo, bo, pP);

    k_tout<<<dim3(Sn/32, Dm/32, Bn), dim3(32, 8)>>>(pP, out);
}

// round 10
// speedup vs baseline: 1.0546x; 1.0007x over previous
#include <cuda_runtime.h>
#include <math.h>

#define Bn 4
#define Dm 1024
#define Sn 2048
#define Hn 16
#define HD 64

// ---------------- scratch (static device memory, no allocs) ----------------
__device__ float g_Xt[Bn*Sn*Dm];  // x + pe, transposed to [B,S,D]
__device__ float g_Q [Bn*Sn*Dm];
__device__ float g_K [Bn*Sn*Dm];
__device__ float g_V [Bn*Sn*Dm];
__device__ float g_AO[Bn*Sn*Dm];  // attention out [B,S,D]
__device__ float g_P [Bn*Sn*Dm];  // out proj [B,S,D]

// ---------------- pos-encoding + transpose: x[b,d,s] -> Xt[b,s,d] ----------
__global__ void k_prep(const float* __restrict__ x){
    __shared__ float t[32][33];
    int b  = blockIdx.z;
    int d0 = blockIdx.y * 32, s0 = blockIdx.x * 32;
    const float NEG = -9.210340371976184f / (float)Dm;   // -ln(10000)/D
    #pragma unroll
    for (int k = 0; k < 4; k++){
        int d = d0 + threadIdx.y + k*8;
        int s = s0 + threadIdx.x;
        float v = x[(b*Dm + d)*Sn + s];
        int de = d & ~1;
        float ang = (float)s * __expf((float)de * NEG);
        v += (d & 1) ? cosf(ang) : sinf(ang);
        t[threadIdx.y + k*8][threadIdx.x] = v;
    }
    __syncthreads();
    #pragma unroll
    for (int k = 0; k < 4; k++){
        int s = s0 + threadIdx.y + k*8;
        int d = d0 + threadIdx.x;
        g_Xt[(b*Sn + s)*Dm + d] = t[threadIdx.x][threadIdx.y + k*8];
    }
}

// ---------------- SGEMM: C[n,m] = sum_k A[n,k]*W[m,k] + bias[m] ------------
// A: [8192,1024] row-major, W: [1024,1024] row-major, NT gemm.
// 128x128 tile, BK=16, 256 threads, 8x8 microtile, strided mapping.
__global__ __launch_bounds__(256) void k_gemm(const float* __restrict__ A,
                                              const float* __restrict__ W,
                                              const float* __restrict__ bias,
                                              float* __restrict__ C){
    __shared__ float As[128][17];
    __shared__ float Bs[128][17];
    int tid = threadIdx.x;
    int cx = tid & 15, ry = tid >> 4;            // cols strided by 16 via cx, rows via ry
    int m0 = blockIdx.x * 128, n0 = blockIdx.y * 128;

    float acc[8][8];
    #pragma unroll
    for (int i = 0; i < 8; i++)
        #pragma unroll
        for (int j = 0; j < 8; j++) acc[i][j] = 0.f;

    for (int kt = 0; kt < Dm/16; kt++){
        int k0 = kt * 16;
        #pragma unroll
        for (int r = 0; r < 2; r++){
            int f   = tid + 256*r;               // 0..511 float4 slots
            int row = f >> 2, kq = f & 3;
            float4 av = *(const float4*)(A + (n0+row)*Dm + k0 + 4*kq);
            As[row][4*kq+0]=av.x; As[row][4*kq+1]=av.y;
            As[row][4*kq+2]=av.z; As[row][4*kq+3]=av.w;
            float4 bv = *(const float4*)(W + (m0+row)*Dm + k0 + 4*kq);
            Bs[row][4*kq+0]=bv.x; Bs[row][4*kq+1]=bv.y;
            Bs[row][4*kq+2]=bv.z; Bs[row][4*kq+3]=bv.w;
        }
        __syncthreads();
        #pragma unroll
        for (int kk = 0; kk < 16; kk++){
            float a[8], b[8];
            #pragma unroll
            for (int i = 0; i < 8; i++) a[i] = As[ry + 16*i][kk];   // broadcast
            #pragma unroll
            for (int j = 0; j < 8; j++) b[j] = Bs[cx + 16*j][kk];   // lane-consecutive
            #pragma unroll
            for (int i = 0; i < 8; i++)
                #pragma unroll
                for (int j = 0; j < 8; j++) acc[i][j] += a[i]*b[j];
        }
        __syncthreads();
    }

    float bb[8];
    #pragma unroll
    for (int j = 0; j < 8; j++) bb[j] = bias[m0 + cx + 16*j];
    #pragma unroll
    for (int i = 0; i < 8; i++){
        int n = n0 + ry + 16*i;
        #pragma unroll
        for (int j = 0; j < 8; j++)
            C[n*Dm + m0 + cx + 16*j] = acc[i][j] + bb[j];
    }
}

// ---------------- flash attention fp32 -------------------------------------
// BM=128 queries, BN=64 keys, hd=64, 128 threads (16 qx x 8 ky), 8x8 microtile.
// q rows = qx + 16*i (strided), key/hd cols = 8*ky + j (consecutive).
#define QS_LD 65
#define KS_LD 68
__global__ __launch_bounds__(128) void k_flash(const float* __restrict__ Q,
                                               const float* __restrict__ K,
                                               const float* __restrict__ V,
                                               float* __restrict__ O){
    extern __shared__ float sm[];
    float* Qs   = sm;                      // [128][65]  (q, d)
    float* Ps   = Qs + 128*QS_LD;          // [128][65]  scores/probs (q, k)
    float* Ks   = Ps + 128*QS_LD;          // [64][68]   (k, d)
    float* Vs   = Ks + 64*KS_LD;           // [64][68]   (k, d)
    float* corr = Vs + 64*KS_LD;           // [128]

    int tid = threadIdx.x;
    int qx = tid & 15, ky = tid >> 4;
    int q0 = blockIdx.x * 128;
    int h  = blockIdx.y, b = blockIdx.z;
    int base = (b*Sn)*Dm + h*HD;           // + s*Dm + d

    // load Q tile, fold 1/sqrt(64) scale
    #pragma unroll
    for (int r = 0; r < 16; r++){
        int f = tid + 128*r;               // 2048 float4 slots
        int q = f >> 4, dq = f & 15;
        float4 v = *(const float4*)(Q + base + (q0+q)*Dm + 4*dq);
        float* dst = &Qs[q*QS_LD + 4*dq];
        dst[0]=v.x*0.125f; dst[1]=v.y*0.125f; dst[2]=v.z*0.125f; dst[3]=v.w*0.125f;
    }

    float m = -INFINITY, l = 0.f;
    float oacc[8][8];
    #pragma unroll
    for (int i = 0; i < 8; i++)
        #pragma unroll
        for (int j = 0; j < 8; j++) oacc[i][j] = 0.f;

    for (int kt = 0; kt < Sn/64; kt++){
        __syncthreads();                   // prev PV done before overwrite
        #pragma unroll
        for (int r = 0; r < 8; r++){
            int f = tid + 128*r;           // 1024 float4 slots
            int kk = f >> 4, dq = f & 15;
            int g = base + (kt*64 + kk)*Dm + 4*dq;
            *(float4*)&Ks[kk*KS_LD + 4*dq] = *(const float4*)(K + g);
            *(float4*)&Vs[kk*KS_LD + 4*dq] = *(const float4*)(V + g);
        }
        __syncthreads();

        // S = Q K^T (scaled)
        float sacc[8][8];
        #pragma unroll
        for (int i = 0; i < 8; i++)
            #pragma unroll
            for (int j = 0; j < 8; j++) sacc[i][j] = 0.f;
        #pragma unroll 4
        for (int kk = 0; kk < 64; kk++){
            float a[8], bv[8];
            #pragma unroll
            for (int i = 0; i < 8; i++) a[i]  = Qs[(qx + 16*i)*QS_LD + kk];
            #pragma unroll
            for (int j = 0; j < 8; j++) bv[j] = Ks[(8*ky + j)*KS_LD + kk];
            #pragma unroll
            for (int i = 0; i < 8; i++)
                #pragma unroll
                for (int j = 0; j < 8; j++) sacc[i][j] += a[i]*bv[j];
        }
        #pragma unroll
        for (int i = 0; i < 8; i++)
            #pragma unroll
            for (int j = 0; j < 8; j++)
                Ps[(qx + 16*i)*QS_LD + 8*ky + j] = sacc[i][j];
        __syncthreads();

        // online softmax: thread tid owns row q=tid
        {
            float* row = &Ps[tid*QS_LD];
            float mt = row[0];
            #pragma unroll 8
            for (int k = 1; k < 64; k++) mt = fmaxf(mt, row[k]);
            float mn = fmaxf(m, mt);
            float c  = __expf(m - mn);
            float sum = 0.f;
            #pragma unroll 8
            for (int k = 0; k < 64; k++){
                float p = __expf(row[k] - mn);
                row[k] = p;
                sum += p;
            }
            l = l*c + sum;
            m = mn;
            corr[tid] = c;
        }
        __syncthreads();

        // rescale O, accumulate P·V
        float cr[8];
        #pragma unroll
        for (int i = 0; i < 8; i++) cr[i] = corr[qx + 16*i];
        #pragma unroll
        for (int i = 0; i < 8; i++)
            #pragma unroll
            for (int j = 0; j < 8; j++) oacc[i][j] *= cr[i];
        #pragma unroll 4
        for (int kk = 0; kk < 64; kk++){
            float p[8], vv[8];
            #pragma unroll
            for (int i = 0; i < 8; i++) p[i]  = Ps[(qx + 16*i)*QS_LD + kk];
            #pragma unroll
            for (int j = 0; j < 8; j++) vv[j] = Vs[kk*KS_LD + 8*ky + j];
            #pragma unroll
            for (int i = 0; i < 8; i++)
                #pragma unroll
                for (int j = 0; j < 8; j++) oacc[i][j] += p[i]*vv[j];
        }
    }

    // finalize: 1/l per row, stage through smem for coalesced store
    __syncthreads();
    corr[tid] = 1.f / l;
    __syncthreads();
    float li[8];
    #pragma unroll
    for (int i = 0; i < 8; i++) li[i] = corr[qx + 16*i];
    #pragma unroll
    for (int i = 0; i < 8; i++)
        #pragma unroll
        for (int j = 0; j < 8; j++)
            Ps[(qx + 16*i)*QS_LD + 8*ky + j] = oacc[i][j] * li[i];
    __syncthreads();
    #pragma unroll
    for (int r = 0; r < 16; r++){
        int f = tid + 128*r;
        int q = f >> 4, dc = (f & 15) * 4;
        float4 o;
        o.x = Ps[q*QS_LD + dc + 0];
        o.y = Ps[q*QS_LD + dc + 1];
        o.z = Ps[q*QS_LD + dc + 2];
        o.w = Ps[q*QS_LD + dc + 3];
        *(float4*)(O + base + (q0+q)*Dm + dc) = o;
    }
}

// ---------------- final transpose: P[b,s,d] -> out[b,d,s] ------------------
__global__ void k_tout(const float* __restrict__ P, float* __restrict__ out){
    __shared__ float t[32][33];
    int b  = blockIdx.z;
    int d0 = blockIdx.y * 32, s0 = blockIdx.x * 32;
    #pragma unroll
    for (int k = 0; k < 4; k++){
        int s = s0 + threadIdx.y + k*8;
        int d = d0 + threadIdx.x;
        t[threadIdx.y + k*8][threadIdx.x] = P[(b*Sn + s)*Dm + d];
    }
    __syncthreads();
    #pragma unroll
    for (int k = 0; k < 4; k++){
        int d = d0 + threadIdx.y + k*8;
        int s = s0 + threadIdx.x;
        out[(b*Dm + d)*Sn + s] = t[threadIdx.x][threadIdx.y + k*8];
    }
}

// ---------------- launch ----------------------------------------------------
extern "C" void kernel_launch(void* const* d_in, const int* in_sizes, int n_in,
                              void* d_out, int out_size){
    const float* x  = (const float*)d_in[0];
    const float* Wq = (const float*)d_in[1];
    const float* bq = (const float*)d_in[2];
    const float* Wk = (const float*)d_in[3];
    const float* bk = (const float*)d_in[4];
    const float* Wv = (const float*)d_in[5];
    const float* bv = (const float*)d_in[6];
    const float* Wo = (const float*)d_in[7];
    const float* bo = (const float*)d_in[8];
    float* out = (float*)d_out;

    float *pXt, *pQ, *pK, *pV, *pAO, *pP;
    cudaGetSymbolAddress((void**)&pXt, g_Xt);
    cudaGetSymbolAddress((void**)&pQ,  g_Q);
    cudaGetSymbolAddress((void**)&pK,  g_K);
    cudaGetSymbolAddress((void**)&pV,  g_V);
    cudaGetSymbolAddress((void**)&pAO, g_AO);
    cudaGetSymbolAddress((void**)&pP,  g_P);

    const int FLASH_SMEM = (128*QS_LD + 128*QS_LD + 64*KS_LD + 64*KS_LD + 128) * 4;
    cudaFuncSetAttribute(k_flash, cudaFuncAttributeMaxDynamicSharedMemorySize, FLASH_SMEM);

    k_prep<<<dim3(Sn/32, Dm/32, Bn), dim3(32, 8)>>>(x);

    dim3 gg(Dm/128, (Bn*Sn)/128);
    k_gemm<<<gg, 256>>>(pXt, Wq, bq, pQ);
    k_gemm<<<gg, 256>>>(pXt, Wk, bk, pK);
    k_gemm<<<gg, 256>>>(pXt, Wv, bv, pV);

    k_flash<<<dim3(Sn/128, Hn, Bn), 128, FLASH_SMEM>>>(pQ, pK, pV, pAO);

    k_gemm<<<gg, 256>>>(pAO, Wo, bo, pP);

    k_tout<<<dim3(Sn/32, Dm/32, Bn), dim3(32, 8)>>>(pP, out);
}